// round 15
// baseline (speedup 1.0000x reference)
#include <cuda_runtime.h>
#include <cuda_fp16.h>
#include <math.h>
#include <stdint.h>

#define EMB   1024
#define HEADS 16
#define HSZ   64
#define BATCH 4
#define SEQ   2048
#define MTOK  (BATCH * SEQ)   // 8192 token rows

// scratch floats: xh(4M) wk/wq/wv/wo(4x.5M) gkh gqh gvh gyh(4x4M) = 22M floats
__device__ float g_scratch[22ull * 1024 * 1024];

__device__ __forceinline__ void mma_f16(float* c, const uint32_t* a,
                                        uint32_t b0, uint32_t b1) {
    asm volatile(
        "mma.sync.aligned.m16n8k16.row.col.f32.f16.f16.f32 "
        "{%0,%1,%2,%3}, {%4,%5,%6,%7}, {%8,%9}, {%0,%1,%2,%3};\n"
        : "+f"(c[0]), "+f"(c[1]), "+f"(c[2]), "+f"(c[3])
        : "r"(a[0]), "r"(a[1]), "r"(a[2]), "r"(a[3]), "r"(b0), "r"(b1));
}
__device__ __forceinline__ void cp_async16(uint32_t saddr, const void* gaddr) {
    asm volatile("cp.async.cg.shared.global [%0], [%1], 16;\n"
                 :: "r"(saddr), "l"(gaddr));
}
__device__ __forceinline__ void cp_commit() {
    asm volatile("cp.async.commit_group;\n");
}
template <int N>
__device__ __forceinline__ void cp_wait() {
    asm volatile("cp.async.wait_group %0;\n" :: "n"(N));
}
__device__ __forceinline__ uint32_t smem_u32(const void* p) {
    uint32_t a;
    asm("{ .reg .u64 t; cvta.to.shared.u64 t, %1; cvt.u32.u64 %0, t; }"
        : "=r"(a) : "l"(p));
    return a;
}
__device__ __forceinline__ uint32_t pack_h2(float a, float b) {
    __half2 h = __floats2half2_rn(a, b);
    return *(uint32_t*)&h;
}
// packed fp16 exp2: 2 elements per MUFU op; output is a ready mma fragment
__device__ __forceinline__ uint32_t ex2_h2(float a, float b) {
    uint32_t h = pack_h2(a, b);
    uint32_t r;
    asm("ex2.approx.f16x2 %0, %1;" : "=r"(r) : "r"(h));
    return r;
}
__device__ __forceinline__ void ldsm4(uint32_t& r0, uint32_t& r1,
                                      uint32_t& r2, uint32_t& r3, uint32_t a) {
    asm volatile("ldmatrix.sync.aligned.m8n8.x4.shared.b16 {%0,%1,%2,%3}, [%4];"
                 : "=r"(r0), "=r"(r1), "=r"(r2), "=r"(r3) : "r"(a));
}
__device__ __forceinline__ void ldsm4t(uint32_t& r0, uint32_t& r1,
                                       uint32_t& r2, uint32_t& r3, uint32_t a) {
    asm volatile("ldmatrix.sync.aligned.m8n8.x4.trans.shared.b16 {%0,%1,%2,%3}, [%4];"
                 : "=r"(r0), "=r"(r1), "=r"(r2), "=r"(r3) : "r"(a));
}

// ---------------------------------------------------------------------------
// One-shot fp32 -> fp16 convert of x + all 4 weights (single launch).
// ---------------------------------------------------------------------------
#define X4  (MTOK * EMB / 4)          // 2097152
#define W4  (EMB * EMB / 4)           // 262144

__global__ __launch_bounds__(256)
void conv_all(const float* __restrict__ x,  const float* __restrict__ Wk,
              const float* __restrict__ Wq, const float* __restrict__ Wv,
              const float* __restrict__ Wo,
              __half* __restrict__ xh,  __half* __restrict__ wkh,
              __half* __restrict__ wqh, __half* __restrict__ wvh,
              __half* __restrict__ woh)
{
    const int total = X4 + 4 * W4;
    int i = blockIdx.x * 256 + threadIdx.x;
    const int stride = gridDim.x * 256;
    for (; i < total; i += stride) {
        const float* src; __half* dst; int off;
        if (i < X4) { src = x; dst = xh; off = i; }
        else {
            const int j = i - X4;
            const int w = j >> 18;
            off = j & (W4 - 1);
            src = (w == 0) ? Wk : (w == 1) ? Wq : (w == 2) ? Wv : Wo;
            dst = (w == 0) ? wkh : (w == 1) ? wqh : (w == 2) ? wvh : woh;
        }
        float4 v = ((const float4*)src)[off];
        uint2 o;
        o.x = pack_h2(v.x, v.y);
        o.y = pack_h2(v.z, v.w);
        ((uint2*)dst)[off] = o;
    }
}

// ---------------------------------------------------------------------------
// FP16 GEMM core (fp32 accumulate). 128x128 tile, BK=64, 8 warps, m16n8k16,
// 3-stage cp.async @ 2 CTAs/SM. (R14 config — best so far.)
// ---------------------------------------------------------------------------
#define GSTAGES 3
#define BKH     64
#define ROWB    144                     // 64 data halves + 8 pad = 144 bytes
#define STG_B   (128 * ROWB)            // 18432 B per operand per stage
#define GEMM_SMEM (GSTAGES * 2 * STG_B) // 110592 B (2 CTAs/SM fits 228KB)

#define GFILL(stg, kc) do {                                                  \
    _Pragma("unroll")                                                        \
    for (int i_ = 0; i_ < 8; i_++) {                                         \
        const int idx_ = tid + i_ * 256;                                     \
        const int op_  = idx_ >> 10;                                         \
        const int r_   = (idx_ & 1023) >> 3;                                 \
        const int q_   = idx_ & 7;                                           \
        const __half* g_ = (op_ ? B + (size_t)(bn + r_) * K                  \
                                : A + (size_t)(bm + r_) * K)                 \
                           + (kc) * BKH + q_ * 8;                            \
        cp_async16(data + (stg) * 2 * STG_B + op_ * STG_B                    \
                   + r_ * ROWB + q_ * 16, g_);                               \
    }                                                                        \
} while (0)

#define GEMM_BODY                                                             \
    extern __shared__ char dyn_smem[];                                        \
    const uint32_t data = smem_u32(dyn_smem);                                 \
    const int lane = tid & 31;                                                \
    const int wid  = tid >> 5;                                                \
    const int wm   = (wid >> 2) * 64;                                         \
    const int wn   = (wid & 3) * 32;                                          \
    const int lr   = lane >> 2;                                               \
    const int lc   = lane & 3;                                                \
    const uint32_t arow = ((lane >> 3) & 1) * 8 + (lane & 7);                 \
    const uint32_t achk = (lane >> 4) * 16;                                   \
    uint32_t aoff[4], boff[4];                                                \
    _Pragma("unroll")                                                         \
    for (int mt = 0; mt < 4; mt++)                                            \
        aoff[mt] = (wm + mt * 16 + arow) * ROWB + achk;                       \
    _Pragma("unroll")                                                         \
    for (int nt = 0; nt < 4; nt++)                                            \
        boff[nt] = (wn + nt * 8 + (lane & 7)) * ROWB + (lane >> 3) * 16;      \
    float acc[4][4][4];                                                       \
    _Pragma("unroll")                                                         \
    for (int i = 0; i < 4; i++)                                               \
        _Pragma("unroll")                                                     \
        for (int j = 0; j < 4; j++)                                           \
            _Pragma("unroll")                                                 \
            for (int r = 0; r < 4; r++) acc[i][j][r] = 0.0f;                  \
    _Pragma("unroll")                                                         \
    for (int s = 0; s < GSTAGES - 1; s++) { GFILL(s, s); cp_commit(); }       \
    const int nchunk = K / BKH;                                               \
    for (int it = 0; it < nchunk; it++) {                                     \
        cp_wait<GSTAGES - 2>();                                               \
        __syncthreads();                                                      \
        const int nxt = it + GSTAGES - 1;                                     \
        if (nxt < nchunk) GFILL(nxt % GSTAGES, nxt);                          \
        cp_commit();                                                          \
        const uint32_t asb = data + (it % GSTAGES) * 2 * STG_B;               \
        const uint32_t bsb = asb + STG_B;                                     \
        _Pragma("unroll")                                                     \
        for (int ks2 = 0; ks2 < 2; ks2++) {                                   \
            uint32_t bfr[4][4];                                               \
            _Pragma("unroll")                                                 \
            for (int nt = 0; nt < 4; nt++)                                    \
                ldsm4(bfr[nt][0], bfr[nt][1], bfr[nt][2], bfr[nt][3],         \
                      bsb + boff[nt] + ks2 * 64);                             \
            _Pragma("unroll")                                                 \
            for (int ks = 0; ks < 2; ks++) {                                  \
                uint32_t afr[4][4];                                           \
                _Pragma("unroll")                                             \
                for (int mt = 0; mt < 4; mt++)                                \
                    ldsm4(afr[mt][0], afr[mt][1], afr[mt][2], afr[mt][3],     \
                          asb + aoff[mt] + ks2 * 64 + ks * 32);               \
                _Pragma("unroll")                                             \
                for (int mt = 0; mt < 4; mt++)                                \
                    _Pragma("unroll")                                         \
                    for (int nt = 0; nt < 4; nt++)                            \
                        mma_f16(acc[mt][nt], afr[mt],                         \
                                bfr[nt][2 * ks], bfr[nt][2 * ks + 1]);        \
            }                                                                 \
        }                                                                     \
    }

// ---- fused QKV GEMM with per-head LayerNorm folded into the epilogue ----
__global__ __launch_bounds__(256, 2)
void gemm_qkv(const __half* __restrict__ A,
              const __half* __restrict__ Wk2, const __half* __restrict__ Wq2,
              const __half* __restrict__ Wv2,
              __half* __restrict__ Ck, __half* __restrict__ Cq,
              __half* __restrict__ Cv,
              const float* __restrict__ kgv, const float* __restrict__ kbv,
              const float* __restrict__ qgv, const float* __restrict__ qbv,
              float scaleK, float scaleQ)
{
    const int tid = threadIdx.x;
    const int K = EMB, N = EMB;
    const int bm = blockIdx.y * 128;
    const int bn_raw = blockIdx.x * 128;
    const int sec = bn_raw >> 10;
    const int bn  = bn_raw & 1023;
    const __half* B = (sec == 0) ? Wk2 : (sec == 1) ? Wq2 : Wv2;
    __half* C       = (sec == 0) ? Ck  : (sec == 1) ? Cq  : Cv;

    GEMM_BODY

    if (sec < 2) {
        const float* g  = (sec == 0) ? kgv : qgv;
        const float* bb = (sec == 0) ? kbv : qbv;
        const float scale = (sec == 0) ? scaleK : scaleQ;

        cp_wait<0>();
        __syncthreads();
        float2* part = (float2*)dyn_smem;

        float ss[4][2], qq[4][2];
        #pragma unroll
        for (int mt = 0; mt < 4; mt++) {
            #pragma unroll
            for (int hf = 0; hf < 2; hf++) {
                float s = 0.f, q = 0.f;
                #pragma unroll
                for (int nt = 0; nt < 4; nt++) {
                    const float a0 = acc[mt][nt][2 * hf];
                    const float a1 = acc[mt][nt][2 * hf + 1];
                    s += a0 + a1;
                    q += a0 * a0 + a1 * a1;
                }
                s += __shfl_xor_sync(0xffffffffu, s, 1);
                s += __shfl_xor_sync(0xffffffffu, s, 2);
                q += __shfl_xor_sync(0xffffffffu, q, 1);
                q += __shfl_xor_sync(0xffffffffu, q, 2);
                ss[mt][hf] = s;
                qq[mt][hf] = q;
                if (lc == 0)
                    part[wid * 64 + mt * 16 + hf * 8 + lr] = make_float2(s, q);
            }
        }
        __syncthreads();

        float mean[4][2], rstd[4][2];
        #pragma unroll
        for (int mt = 0; mt < 4; mt++) {
            #pragma unroll
            for (int hf = 0; hf < 2; hf++) {
                const float2 pr = part[(wid ^ 1) * 64 + mt * 16 + hf * 8 + lr];
                const float S  = ss[mt][hf] + pr.x;
                const float Q2 = qq[mt][hf] + pr.y;
                const float mn = S * (1.0f / 64.0f);
                const float vr = Q2 * (1.0f / 64.0f) - mn * mn;
                mean[mt][hf] = mn;
                rstd[mt][hf] = rsqrtf(vr + 1e-5f);
            }
        }

        #pragma unroll
        for (int mt = 0; mt < 4; mt++) {
            const int row = bm + wm + mt * 16 + lr;
            const float mA = mean[mt][0], rA = rstd[mt][0];
            const float mB = mean[mt][1], rB = rstd[mt][1];
            #pragma unroll
            for (int nt = 0; nt < 4; nt++) {
                const int col  = bn + wn + nt * 8 + lc * 2;
                const int gdim = (wn + nt * 8 + lc * 2) & 63;
                const float g0 = g[gdim],  g1 = g[gdim + 1];
                const float b0 = bb[gdim], b1 = bb[gdim + 1];
                const float oA0 = ((acc[mt][nt][0] - mA) * rA * g0 + b0) * scale;
                const float oA1 = ((acc[mt][nt][1] - mA) * rA * g1 + b1) * scale;
                const float oB0 = ((acc[mt][nt][2] - mB) * rB * g0 + b0) * scale;
                const float oB1 = ((acc[mt][nt][3] - mB) * rB * g1 + b1) * scale;
                *(uint32_t*)(C + (size_t)row * N + col)       = pack_h2(oA0, oA1);
                *(uint32_t*)(C + (size_t)(row + 8) * N + col) = pack_h2(oB0, oB1);
            }
        }
    } else {
        #pragma unroll
        for (int mt = 0; mt < 4; mt++) {
            const int row = bm + wm + mt * 16 + lr;
            #pragma unroll
            for (int nt = 0; nt < 4; nt++) {
                const int col = bn + wn + nt * 8 + lc * 2;
                *(uint32_t*)(C + (size_t)row * N + col) =
                    pack_h2(acc[mt][nt][0], acc[mt][nt][1]);
                *(uint32_t*)(C + (size_t)(row + 8) * N + col) =
                    pack_h2(acc[mt][nt][2], acc[mt][nt][3]);
            }
        }
    }
}

// ---- output projection: fp32 out + bias ----
__global__ __launch_bounds__(256, 2)
void gemm_f16(const __half* __restrict__ A, const __half* __restrict__ B,
              const float* __restrict__ bias, float* __restrict__ C,
              int M, int N, int K)
{
    const int tid = threadIdx.x;
    const int bm  = blockIdx.y * 128;
    const int bn  = blockIdx.x * 128;

    GEMM_BODY

    #pragma unroll
    for (int mt = 0; mt < 4; mt++) {
        const int row = bm + wm + mt * 16 + lr;
        #pragma unroll
        for (int nt = 0; nt < 4; nt++) {
            const int col = bn + wn + nt * 8 + lc * 2;
            const float b0 = bias[col], b1 = bias[col + 1];
            *(float2*)(C + (size_t)row * N + col) =
                make_float2(acc[mt][nt][0] + b0, acc[mt][nt][1] + b1);
            *(float2*)(C + (size_t)(row + 8) * N + col) =
                make_float2(acc[mt][nt][2] + b0, acc[mt][nt][3] + b1);
        }
    }
}

// ---------------------------------------------------------------------------
// FP16 flash attention, BR=128 (8 warps x 16 rows), D=64.
// 128-key SUPER-TILES: 3-slot ring of [K0,K1,V0,V1] (36.9KB/slot), ONE
// barrier per 128 keys; two 64-key subtiles processed back-to-back.
// ldmatrix fragments, packed f16 exp2, exp2-domain softmax.
// ---------------------------------------------------------------------------
#define FROWB 144                 // smem row: 64 halves + 8 pad
#define FTILE (64 * FROWB)        // 9216 B per 64-key operand subtile
#define SSLOT (4 * FTILE)         // 36864 B per super-slot [K0 K1 V0 V1]

__global__ __launch_bounds__(256)
void flash_attn2(const __half* __restrict__ Q, const __half* __restrict__ K,
                 const __half* __restrict__ V, __half* __restrict__ Oh)
{
    __shared__ __align__(16) char kvbuf[3 * SSLOT];  // 110.6 KB

    const int qb = blockIdx.x;          // 128-row query tile
    const int h  = blockIdx.y;
    const int b  = blockIdx.z;
    const int tid  = threadIdx.x;
    const int lane = tid & 31;
    const int wid  = tid >> 5;
    const int wm   = wid * 16;
    const int lr   = lane >> 2;
    const int lc   = lane & 3;

    const size_t base = (size_t)b * SEQ * EMB + (size_t)h * HSZ;
    const __half* Qg = Q + base + (size_t)(qb * 128) * EMB;
    const __half* Kg = K + base;
    const __half* Vg = V + base;
    const uint32_t sbase = smem_u32(kvbuf);

    // ---- stage Q through slot0, extract A-frags via ldmatrix ----
    #pragma unroll
    for (int i = 0; i < 4; i++) {
        const int idx = tid + i * 256;
        const int r = idx >> 3, q = idx & 7;
        cp_async16(sbase + r * FROWB + q * 16, Qg + (size_t)r * EMB + q * 8);
    }
    cp_commit();
    cp_wait<0>();
    __syncthreads();

    const uint32_t qrow = wm + ((lane >> 3) & 1) * 8 + (lane & 7);
    const uint32_t qoff = ((lane >> 4) ? 16u : 0u);
    uint32_t qa[4][4];
    #pragma unroll
    for (int kk = 0; kk < 4; kk++)
        ldsm4(qa[kk][0], qa[kk][1], qa[kk][2], qa[kk][3],
              sbase + qrow * FROWB + kk * 32 + qoff);
    __syncthreads();

    // ---- super-tile fill: 128 keys of K and V ----
    // layout within slot: [K sub0][K sub1][V sub0][V sub1]
    #define SFILL(st_, slot_) do {                                           \
        const uint32_t so_ = sbase + (slot_) * SSLOT;                        \
        _Pragma("unroll")                                                    \
        for (int i_ = 0; i_ < 8; i_++) {                                     \
            const int idx_ = tid + i_ * 256;                                 \
            const int op_  = idx_ >> 10;                                     \
            const int r_   = (idx_ >> 3) & 127;                              \
            const int q_   = idx_ & 7;                                       \
            const __half* g_ = (op_ ? Vg : Kg)                               \
                + (size_t)((st_) * 128 + r_) * EMB + q_ * 8;                 \
            cp_async16(so_ + op_ * 2 * FTILE + (r_ >> 6) * FTILE             \
                       + (r_ & 63) * FROWB + q_ * 16, g_);                   \
        }                                                                    \
    } while (0)

    SFILL(0, 0);
    cp_commit();
    if (qb >= 1) SFILL(1, 1);
    cp_commit();

    float o[8][4];
    #pragma unroll
    for (int i = 0; i < 8; i++)
        #pragma unroll
        for (int j = 0; j < 4; j++) o[i][j] = 0.0f;
    float m0 = -INFINITY, m1 = -INFINITY, l0 = 0.0f, l1 = 0.0f;

    const uint32_t krow = (lane & 7);
    const uint32_t ktil = (lane >> 3) * 16;
    const uint32_t vrow = ((lane >> 3) & 1) * 8 + (lane & 7);
    const uint32_t voff = ((lane >> 4) ? 16u : 0u);

    for (int st = 0; st <= qb; st++) {
        const int slot = st % 3;
        cp_wait<1>();
        __syncthreads();
        const uint32_t slotb = sbase + slot * SSLOT;

        #pragma unroll
        for (int sub = 0; sub < 2; sub++) {
            const uint32_t ksb = slotb + sub * FTILE;

            // ---- S = Q K^T ----
            float s[8][4];
            #pragma unroll
            for (int nt = 0; nt < 8; nt++)
                #pragma unroll
                for (int j = 0; j < 4; j++) s[nt][j] = 0.0f;

            #pragma unroll
            for (int nt = 0; nt < 8; nt++) {
                const uint32_t abase = ksb + (nt * 8 + krow) * FROWB + ktil;
                #pragma unroll
                for (int hh = 0; hh < 2; hh++) {
                    uint32_t b0, b1, b2, b3;
                    ldsm4(b0, b1, b2, b3, abase + hh * 64);
                    mma_f16(s[nt], qa[2 * hh],     b0, b1);
                    mma_f16(s[nt], qa[2 * hh + 1], b2, b3);
                }
            }

            // prefetch super-tile st+2 right after first S-mma batch
            if (sub == 0) {
                if (st + 2 <= qb) SFILL(st + 2, (st + 2) % 3);
                cp_commit();
            }

            // ---- causal mask (only the last super-tile) ----
            if (st == qb) {
                const int rg = qb * 128 + wm + lr;
                const int kt = 2 * st + sub;
                #pragma unroll
                for (int nt = 0; nt < 8; nt++) {
                    const int cg = kt * 64 + nt * 8 + 2 * lc;
                    if (cg     > rg)     s[nt][0] = -1e30f;
                    if (cg + 1 > rg)     s[nt][1] = -1e30f;
                    if (cg     > rg + 8) s[nt][2] = -1e30f;
                    if (cg + 1 > rg + 8) s[nt][3] = -1e30f;
                }
            }

            // ---- online softmax, exp2 domain, packed f16 exponentials ----
            float mx0 = -INFINITY, mx1 = -INFINITY;
            #pragma unroll
            for (int nt = 0; nt < 8; nt++) {
                mx0 = fmaxf(mx0, fmaxf(s[nt][0], s[nt][1]));
                mx1 = fmaxf(mx1, fmaxf(s[nt][2], s[nt][3]));
            }
            mx0 = fmaxf(mx0, __shfl_xor_sync(0xffffffffu, mx0, 1));
            mx0 = fmaxf(mx0, __shfl_xor_sync(0xffffffffu, mx0, 2));
            mx1 = fmaxf(mx1, __shfl_xor_sync(0xffffffffu, mx1, 1));
            mx1 = fmaxf(mx1, __shfl_xor_sync(0xffffffffu, mx1, 2));

            const float m0n = fmaxf(m0, mx0);
            const float m1n = fmaxf(m1, mx1);
            const float c0 = exp2f(m0 - m0n);
            const float c1 = exp2f(m1 - m1n);
            m0 = m0n; m1 = m1n;
            #pragma unroll
            for (int nt = 0; nt < 8; nt++) {
                o[nt][0] *= c0; o[nt][1] *= c0;
                o[nt][2] *= c1; o[nt][3] *= c1;
            }

            uint32_t ph[8][2];
            float la0 = 0.f, lb0 = 0.f, la1 = 0.f, lb1 = 0.f;
            #pragma unroll
            for (int nt = 0; nt < 8; nt++) {
                ph[nt][0] = ex2_h2(s[nt][0] - m0, s[nt][1] - m0);
                ph[nt][1] = ex2_h2(s[nt][2] - m1, s[nt][3] - m1);
                const float2 f0 = __half22float2(*(__half2*)&ph[nt][0]);
                const float2 f1 = __half22float2(*(__half2*)&ph[nt][1]);
                if (nt & 1) { lb0 += f0.x + f0.y; lb1 += f1.x + f1.y; }
                else        { la0 += f0.x + f0.y; la1 += f1.x + f1.y; }
            }
            l0 = l0 * c0 + (la0 + lb0);
            l1 = l1 * c1 + (la1 + lb1);

            // ---- O += P V ----
            const uint32_t vsl = slotb + 2 * FTILE + sub * FTILE;
            #pragma unroll
            for (int kk = 0; kk < 4; kk++) {
                uint32_t pa[4];
                pa[0] = ph[2 * kk][0];
                pa[1] = ph[2 * kk][1];
                pa[2] = ph[2 * kk + 1][0];
                pa[3] = ph[2 * kk + 1][1];
                const uint32_t vaddr0 = vsl + (kk * 16 + vrow) * FROWB + voff;
                #pragma unroll
                for (int j = 0; j < 4; j++) {
                    uint32_t v0, v1, v2, v3;
                    ldsm4t(v0, v1, v2, v3, vaddr0 + j * 32);
                    mma_f16(o[2 * j],     pa, v0, v1);
                    mma_f16(o[2 * j + 1], pa, v2, v3);
                }
            }
        }
    }

    // ---- finalize ----
    l0 += __shfl_xor_sync(0xffffffffu, l0, 1);
    l0 += __shfl_xor_sync(0xffffffffu, l0, 2);
    l1 += __shfl_xor_sync(0xffffffffu, l1, 1);
    l1 += __shfl_xor_sync(0xffffffffu, l1, 2);
    const float i0 = 1.0f / l0;
    const float i1 = 1.0f / l1;

    const int row0 = qb * 128 + wm + lr;
    uint32_t* op0 = (uint32_t*)(Oh + base + (size_t)row0 * EMB);
    uint32_t* op1 = (uint32_t*)(Oh + base + (size_t)(row0 + 8) * EMB);
    #pragma unroll
    for (int ntd = 0; ntd < 8; ntd++) {
        const int colw = ntd * 4 + lc;
        op0[colw] = pack_h2(o[ntd][0] * i0, o[ntd][1] * i0);
        op1[colw] = pack_h2(o[ntd][2] * i1, o[ntd][3] * i1);
    }
}

// ---------------------------------------------------------------------------
extern "C" void kernel_launch(void* const* d_in, const int* in_sizes, int n_in,
                              void* d_out, int out_size)
{
    const float* x   = (const float*)d_in[0];
    const float* Wk  = (const float*)d_in[1];
    const float* Wq  = (const float*)d_in[2];
    const float* Wv  = (const float*)d_in[3];
    const float* Wo  = (const float*)d_in[4];
    const float* bo  = (const float*)d_in[5];
    const float* kg  = (const float*)d_in[6];
    const float* kb  = (const float*)d_in[7];
    const float* qg  = (const float*)d_in[8];
    const float* qb  = (const float*)d_in[9];
    float* out = (float*)d_out;

    float* sbase = nullptr;
    cudaGetSymbolAddress((void**)&sbase, g_scratch);
    const size_t MB1 = 1024ull * 1024ull;
    __half* xh  = (__half*)(sbase);
    __half* wkh = (__half*)(sbase + 4 * MB1);
    __half* wqh = (__half*)(sbase + 4 * MB1 + MB1 / 2);
    __half* wvh = (__half*)(sbase + 5 * MB1);
    __half* woh = (__half*)(sbase + 5 * MB1 + MB1 / 2);
    __half* gkh = (__half*)(sbase + 6 * MB1);
    __half* gqh = (__half*)(sbase + 10 * MB1);
    __half* gvh = (__half*)(sbase + 14 * MB1);
    __half* gyh = (__half*)(sbase + 18 * MB1);

    const float SCALE  = 0.17677669529663687f;           // 1024^(-1/4)
    const float SCALEQ = SCALE * 1.4426950408889634f;    // fold log2(e) into Q

    cudaFuncSetAttribute(gemm_qkv,
                         cudaFuncAttributeMaxDynamicSharedMemorySize, GEMM_SMEM);
    cudaFuncSetAttribute(gemm_f16,
                         cudaFuncAttributeMaxDynamicSharedMemorySize, GEMM_SMEM);

    conv_all<<<2048, 256>>>(x, Wk, Wq, Wv, Wo, xh, wkh, wqh, wvh, woh);

    dim3 qkvGrid(3 * EMB / 128, MTOK / 128);   // (24, 64)
    gemm_qkv<<<qkvGrid, 256, GEMM_SMEM>>>(xh, wkh, wqh, wvh, gkh, gqh, gvh,
                                          kg, kb, qg, qb, SCALE, SCALEQ);

    dim3 attnGrid(SEQ / 128, HEADS, BATCH);    // (16, 16, 4)
    flash_attn2<<<attnGrid, 256>>>(gqh, gkh, gvh, gyh);

    dim3 gemmGrid(EMB / 128, MTOK / 128);      // (8, 64)
    gemm_f16<<<gemmGrid, 256, GEMM_SMEM>>>(gyh, woh, bo, out, MTOK, EMB, EMB);
}

// round 16
// speedup vs baseline: 1.0921x; 1.0921x over previous
#include <cuda_runtime.h>
#include <cuda_fp16.h>
#include <math.h>
#include <stdint.h>

#define EMB   1024
#define HEADS 16
#define HSZ   64
#define BATCH 4
#define SEQ   2048
#define MTOK  (BATCH * SEQ)   // 8192 token rows

// scratch floats: xh(4M) wk/wq/wv/wo(4x.5M) gkh gqh gvh gyh(4x4M) = 22M floats
__device__ float g_scratch[22ull * 1024 * 1024];

__device__ __forceinline__ void mma_f16(float* c, const uint32_t* a,
                                        uint32_t b0, uint32_t b1) {
    asm volatile(
        "mma.sync.aligned.m16n8k16.row.col.f32.f16.f16.f32 "
        "{%0,%1,%2,%3}, {%4,%5,%6,%7}, {%8,%9}, {%0,%1,%2,%3};\n"
        : "+f"(c[0]), "+f"(c[1]), "+f"(c[2]), "+f"(c[3])
        : "r"(a[0]), "r"(a[1]), "r"(a[2]), "r"(a[3]), "r"(b0), "r"(b1));
}
__device__ __forceinline__ void cp_async16(uint32_t saddr, const void* gaddr) {
    asm volatile("cp.async.cg.shared.global [%0], [%1], 16;\n"
                 :: "r"(saddr), "l"(gaddr));
}
__device__ __forceinline__ void cp_commit() {
    asm volatile("cp.async.commit_group;\n");
}
template <int N>
__device__ __forceinline__ void cp_wait() {
    asm volatile("cp.async.wait_group %0;\n" :: "n"(N));
}
__device__ __forceinline__ uint32_t smem_u32(const void* p) {
    uint32_t a;
    asm("{ .reg .u64 t; cvta.to.shared.u64 t, %1; cvt.u32.u64 %0, t; }"
        : "=r"(a) : "l"(p));
    return a;
}
__device__ __forceinline__ uint32_t pack_h2(float a, float b) {
    __half2 h = __floats2half2_rn(a, b);
    return *(uint32_t*)&h;
}
// packed fp16 exp2: 2 elements per MUFU op; output is a ready mma fragment
__device__ __forceinline__ uint32_t ex2_h2(float a, float b) {
    uint32_t h = pack_h2(a, b);
    uint32_t r;
    asm("ex2.approx.f16x2 %0, %1;" : "=r"(r) : "r"(h));
    return r;
}
__device__ __forceinline__ void ldsm4(uint32_t& r0, uint32_t& r1,
                                      uint32_t& r2, uint32_t& r3, uint32_t a) {
    asm volatile("ldmatrix.sync.aligned.m8n8.x4.shared.b16 {%0,%1,%2,%3}, [%4];"
                 : "=r"(r0), "=r"(r1), "=r"(r2), "=r"(r3) : "r"(a));
}
__device__ __forceinline__ void ldsm4t(uint32_t& r0, uint32_t& r1,
                                       uint32_t& r2, uint32_t& r3, uint32_t a) {
    asm volatile("ldmatrix.sync.aligned.m8n8.x4.trans.shared.b16 {%0,%1,%2,%3}, [%4];"
                 : "=r"(r0), "=r"(r1), "=r"(r2), "=r"(r3) : "r"(a));
}

// ---------------------------------------------------------------------------
// One-shot fp32 -> fp16 convert of x + all 4 weights (single launch).
// ---------------------------------------------------------------------------
#define X4  (MTOK * EMB / 4)          // 2097152
#define W4  (EMB * EMB / 4)           // 262144

__global__ __launch_bounds__(256)
void conv_all(const float* __restrict__ x,  const float* __restrict__ Wk,
              const float* __restrict__ Wq, const float* __restrict__ Wv,
              const float* __restrict__ Wo,
              __half* __restrict__ xh,  __half* __restrict__ wkh,
              __half* __restrict__ wqh, __half* __restrict__ wvh,
              __half* __restrict__ woh)
{
    const int total = X4 + 4 * W4;
    int i = blockIdx.x * 256 + threadIdx.x;
    const int stride = gridDim.x * 256;
    for (; i < total; i += stride) {
        const float* src; __half* dst; int off;
        if (i < X4) { src = x; dst = xh; off = i; }
        else {
            const int j = i - X4;
            const int w = j >> 18;
            off = j & (W4 - 1);
            src = (w == 0) ? Wk : (w == 1) ? Wq : (w == 2) ? Wv : Wo;
            dst = (w == 0) ? wkh : (w == 1) ? wqh : (w == 2) ? wvh : woh;
        }
        float4 v = ((const float4*)src)[off];
        uint2 o;
        o.x = pack_h2(v.x, v.y);
        o.y = pack_h2(v.z, v.w);
        ((uint2*)dst)[off] = o;
    }
}

// ---------------------------------------------------------------------------
// FP16 GEMM core (fp32 accumulate). 128x128 tile, BK=64, 8 warps, m16n8k16,
// 3-stage cp.async @ 2 CTAs/SM. Prefetch fill issued BETWEEN the two compute
// halves so post-barrier issue slots start with tensor work.
// ---------------------------------------------------------------------------
#define GSTAGES 3
#define BKH     64
#define ROWB    144                     // 64 data halves + 8 pad = 144 bytes
#define STG_B   (128 * ROWB)            // 18432 B per operand per stage
#define GEMM_SMEM (GSTAGES * 2 * STG_B) // 110592 B (2 CTAs/SM fits 228KB)

#define GFILL(stg, kc) do {                                                  \
    _Pragma("unroll")                                                        \
    for (int i_ = 0; i_ < 8; i_++) {                                         \
        const int idx_ = tid + i_ * 256;                                     \
        const int op_  = idx_ >> 10;                                         \
        const int r_   = (idx_ & 1023) >> 3;                                 \
        const int q_   = idx_ & 7;                                           \
        const __half* g_ = (op_ ? B + (size_t)(bn + r_) * K                  \
                                : A + (size_t)(bm + r_) * K)                 \
                           + (kc) * BKH + q_ * 8;                            \
        cp_async16(data + (stg) * 2 * STG_B + op_ * STG_B                    \
                   + r_ * ROWB + q_ * 16, g_);                               \
    }                                                                        \
} while (0)

#define GEMM_HALF(ks2)                                                        \
    do {                                                                      \
        uint32_t bfr[4][4];                                                   \
        _Pragma("unroll")                                                     \
        for (int nt = 0; nt < 4; nt++)                                        \
            ldsm4(bfr[nt][0], bfr[nt][1], bfr[nt][2], bfr[nt][3],             \
                  bsb + boff[nt] + (ks2) * 64);                               \
        _Pragma("unroll")                                                     \
        for (int ks = 0; ks < 2; ks++) {                                      \
            uint32_t afr[4][4];                                               \
            _Pragma("unroll")                                                 \
            for (int mt = 0; mt < 4; mt++)                                    \
                ldsm4(afr[mt][0], afr[mt][1], afr[mt][2], afr[mt][3],         \
                      asb + aoff[mt] + (ks2) * 64 + ks * 32);                 \
            _Pragma("unroll")                                                 \
            for (int mt = 0; mt < 4; mt++)                                    \
                _Pragma("unroll")                                             \
                for (int nt = 0; nt < 4; nt++)                                \
                    mma_f16(acc[mt][nt], afr[mt],                             \
                            bfr[nt][2 * ks], bfr[nt][2 * ks + 1]);            \
        }                                                                     \
    } while (0)

#define GEMM_BODY                                                             \
    extern __shared__ char dyn_smem[];                                        \
    const uint32_t data = smem_u32(dyn_smem);                                 \
    const int lane = tid & 31;                                                \
    const int wid  = tid >> 5;                                                \
    const int wm   = (wid >> 2) * 64;                                         \
    const int wn   = (wid & 3) * 32;                                          \
    const int lr   = lane >> 2;                                               \
    const int lc   = lane & 3;                                                \
    const uint32_t arow = ((lane >> 3) & 1) * 8 + (lane & 7);                 \
    const uint32_t achk = (lane >> 4) * 16;                                   \
    uint32_t aoff[4], boff[4];                                                \
    _Pragma("unroll")                                                         \
    for (int mt = 0; mt < 4; mt++)                                            \
        aoff[mt] = (wm + mt * 16 + arow) * ROWB + achk;                       \
    _Pragma("unroll")                                                         \
    for (int nt = 0; nt < 4; nt++)                                            \
        boff[nt] = (wn + nt * 8 + (lane & 7)) * ROWB + (lane >> 3) * 16;      \
    float acc[4][4][4];                                                       \
    _Pragma("unroll")                                                         \
    for (int i = 0; i < 4; i++)                                               \
        _Pragma("unroll")                                                     \
        for (int j = 0; j < 4; j++)                                           \
            _Pragma("unroll")                                                 \
            for (int r = 0; r < 4; r++) acc[i][j][r] = 0.0f;                  \
    _Pragma("unroll")                                                         \
    for (int s = 0; s < GSTAGES - 1; s++) { GFILL(s, s); cp_commit(); }       \
    const int nchunk = K / BKH;                                               \
    for (int it = 0; it < nchunk; it++) {                                     \
        cp_wait<GSTAGES - 2>();                                               \
        __syncthreads();                                                      \
        const uint32_t asb = data + (it % GSTAGES) * 2 * STG_B;               \
        const uint32_t bsb = asb + STG_B;                                     \
        GEMM_HALF(0);                                                         \
        const int nxt = it + GSTAGES - 1;                                     \
        if (nxt < nchunk) GFILL(nxt % GSTAGES, nxt);                          \
        cp_commit();                                                          \
        GEMM_HALF(1);                                                         \
    }

// ---- fused QKV GEMM with per-head LayerNorm folded into the epilogue ----
__global__ __launch_bounds__(256, 2)
void gemm_qkv(const __half* __restrict__ A,
              const __half* __restrict__ Wk2, const __half* __restrict__ Wq2,
              const __half* __restrict__ Wv2,
              __half* __restrict__ Ck, __half* __restrict__ Cq,
              __half* __restrict__ Cv,
              const float* __restrict__ kgv, const float* __restrict__ kbv,
              const float* __restrict__ qgv, const float* __restrict__ qbv,
              float scaleK, float scaleQ)
{
    const int tid = threadIdx.x;
    const int K = EMB, N = EMB;
    const int bm = blockIdx.y * 128;
    const int bn_raw = blockIdx.x * 128;
    const int sec = bn_raw >> 10;
    const int bn  = bn_raw & 1023;
    const __half* B = (sec == 0) ? Wk2 : (sec == 1) ? Wq2 : Wv2;
    __half* C       = (sec == 0) ? Ck  : (sec == 1) ? Cq  : Cv;

    GEMM_BODY

    if (sec < 2) {
        const float* g  = (sec == 0) ? kgv : qgv;
        const float* bb = (sec == 0) ? kbv : qbv;
        const float scale = (sec == 0) ? scaleK : scaleQ;

        cp_wait<0>();
        __syncthreads();
        float2* part = (float2*)dyn_smem;

        float ss[4][2], qq[4][2];
        #pragma unroll
        for (int mt = 0; mt < 4; mt++) {
            #pragma unroll
            for (int hf = 0; hf < 2; hf++) {
                float s = 0.f, q = 0.f;
                #pragma unroll
                for (int nt = 0; nt < 4; nt++) {
                    const float a0 = acc[mt][nt][2 * hf];
                    const float a1 = acc[mt][nt][2 * hf + 1];
                    s += a0 + a1;
                    q += a0 * a0 + a1 * a1;
                }
                s += __shfl_xor_sync(0xffffffffu, s, 1);
                s += __shfl_xor_sync(0xffffffffu, s, 2);
                q += __shfl_xor_sync(0xffffffffu, q, 1);
                q += __shfl_xor_sync(0xffffffffu, q, 2);
                ss[mt][hf] = s;
                qq[mt][hf] = q;
                if (lc == 0)
                    part[wid * 64 + mt * 16 + hf * 8 + lr] = make_float2(s, q);
            }
        }
        __syncthreads();

        float mean[4][2], rstd[4][2];
        #pragma unroll
        for (int mt = 0; mt < 4; mt++) {
            #pragma unroll
            for (int hf = 0; hf < 2; hf++) {
                const float2 pr = part[(wid ^ 1) * 64 + mt * 16 + hf * 8 + lr];
                const float S  = ss[mt][hf] + pr.x;
                const float Q2 = qq[mt][hf] + pr.y;
                const float mn = S * (1.0f / 64.0f);
                const float vr = Q2 * (1.0f / 64.0f) - mn * mn;
                mean[mt][hf] = mn;
                rstd[mt][hf] = rsqrtf(vr + 1e-5f);
            }
        }

        #pragma unroll
        for (int mt = 0; mt < 4; mt++) {
            const int row = bm + wm + mt * 16 + lr;
            const float mA = mean[mt][0], rA = rstd[mt][0];
            const float mB = mean[mt][1], rB = rstd[mt][1];
            #pragma unroll
            for (int nt = 0; nt < 4; nt++) {
                const int col  = bn + wn + nt * 8 + lc * 2;
                const int gdim = (wn + nt * 8 + lc * 2) & 63;
                const float g0 = g[gdim],  g1 = g[gdim + 1];
                const float b0 = bb[gdim], b1 = bb[gdim + 1];
                const float oA0 = ((acc[mt][nt][0] - mA) * rA * g0 + b0) * scale;
                const float oA1 = ((acc[mt][nt][1] - mA) * rA * g1 + b1) * scale;
                const float oB0 = ((acc[mt][nt][2] - mB) * rB * g0 + b0) * scale;
                const float oB1 = ((acc[mt][nt][3] - mB) * rB * g1 + b1) * scale;
                *(uint32_t*)(C + (size_t)row * N + col)       = pack_h2(oA0, oA1);
                *(uint32_t*)(C + (size_t)(row + 8) * N + col) = pack_h2(oB0, oB1);
            }
        }
    } else {
        #pragma unroll
        for (int mt = 0; mt < 4; mt++) {
            const int row = bm + wm + mt * 16 + lr;
            #pragma unroll
            for (int nt = 0; nt < 4; nt++) {
                const int col = bn + wn + nt * 8 + lc * 2;
                *(uint32_t*)(C + (size_t)row * N + col) =
                    pack_h2(acc[mt][nt][0], acc[mt][nt][1]);
                *(uint32_t*)(C + (size_t)(row + 8) * N + col) =
                    pack_h2(acc[mt][nt][2], acc[mt][nt][3]);
            }
        }
    }
}

// ---- output projection: fp32 out + bias ----
__global__ __launch_bounds__(256, 2)
void gemm_f16(const __half* __restrict__ A, const __half* __restrict__ B,
              const float* __restrict__ bias, float* __restrict__ C,
              int M, int N, int K)
{
    const int tid = threadIdx.x;
    const int bm  = blockIdx.y * 128;
    const int bn  = blockIdx.x * 128;

    GEMM_BODY

    #pragma unroll
    for (int mt = 0; mt < 4; mt++) {
        const int row = bm + wm + mt * 16 + lr;
        #pragma unroll
        for (int nt = 0; nt < 4; nt++) {
            const int col = bn + wn + nt * 8 + lc * 2;
            const float b0 = bias[col], b1 = bias[col + 1];
            *(float2*)(C + (size_t)row * N + col) =
                make_float2(acc[mt][nt][0] + b0, acc[mt][nt][1] + b1);
            *(float2*)(C + (size_t)(row + 8) * N + col) =
                make_float2(acc[mt][nt][2] + b0, acc[mt][nt][3] + b1);
        }
    }
}

// ---------------------------------------------------------------------------
// FP16 flash attention, BR=128 (8 warps x 16 rows), BC=64, D=64.
// 3-slot K/V ring (55.3KB, 2 CTAs/SM), ldmatrix fragments, packed f16 exp2,
// exp2-domain softmax. (R14 config — best measured.)
// ---------------------------------------------------------------------------
#define FROWB 144                 // smem row: 64 halves + 8 pad
#define FTILE (64 * FROWB)        // 9216 B per operand tile

__global__ __launch_bounds__(256)
void flash_attn2(const __half* __restrict__ Q, const __half* __restrict__ K,
                 const __half* __restrict__ V, __half* __restrict__ Oh)
{
    __shared__ __align__(16) char kvbuf[3][2][FTILE];  // 55.3 KB

    const int qb = blockIdx.x;          // 128-row query tile
    const int h  = blockIdx.y;
    const int b  = blockIdx.z;
    const int tid  = threadIdx.x;
    const int lane = tid & 31;
    const int wid  = tid >> 5;
    const int wm   = wid * 16;
    const int lr   = lane >> 2;
    const int lc   = lane & 3;

    const size_t base = (size_t)b * SEQ * EMB + (size_t)h * HSZ;
    const __half* Qg = Q + base + (size_t)(qb * 128) * EMB;
    const __half* Kg = K + base;
    const __half* Vg = V + base;
    const uint32_t sbase = smem_u32(kvbuf);

    // ---- stage Q through slot0, extract A-frags via ldmatrix ----
    #pragma unroll
    for (int i = 0; i < 4; i++) {
        const int idx = tid + i * 256;
        const int r = idx >> 3, q = idx & 7;
        cp_async16(sbase + r * FROWB + q * 16, Qg + (size_t)r * EMB + q * 8);
    }
    cp_commit();
    cp_wait<0>();
    __syncthreads();

    const uint32_t qrow = wm + ((lane >> 3) & 1) * 8 + (lane & 7);
    const uint32_t qoff = ((lane >> 4) ? 16u : 0u);
    uint32_t qa[4][4];
    #pragma unroll
    for (int kk = 0; kk < 4; kk++)
        ldsm4(qa[kk][0], qa[kk][1], qa[kk][2], qa[kk][3],
              sbase + qrow * FROWB + kk * 32 + qoff);
    __syncthreads();

    #define AFILL(kt_, slot_) do {                                           \
        const uint32_t so_ = sbase + (slot_) * 2 * FTILE;                    \
        _Pragma("unroll")                                                    \
        for (int i_ = 0; i_ < 4; i_++) {                                     \
            const int idx_ = tid + i_ * 256;                                 \
            const int op_  = idx_ >> 9;                                      \
            const int r_   = (idx_ >> 3) & 63;                               \
            const int q_   = idx_ & 7;                                       \
            const __half* g_ = (op_ ? Vg : Kg)                               \
                + (size_t)((kt_) * 64 + r_) * EMB + q_ * 8;                  \
            cp_async16(so_ + op_ * FTILE + r_ * FROWB + q_ * 16, g_);        \
        }                                                                    \
    } while (0)

    AFILL(0, 0);
    cp_commit();
    AFILL(1, 1);
    cp_commit();

    float o[8][4];
    #pragma unroll
    for (int i = 0; i < 8; i++)
        #pragma unroll
        for (int j = 0; j < 4; j++) o[i][j] = 0.0f;
    float m0 = -INFINITY, m1 = -INFINITY, l0 = 0.0f, l1 = 0.0f;

    const uint32_t krow = (lane & 7);
    const uint32_t ktil = (lane >> 3) * 16;
    const uint32_t vrow = ((lane >> 3) & 1) * 8 + (lane & 7);
    const uint32_t voff = ((lane >> 4) ? 16u : 0u);
    const int lastkt = 2 * qb + 1;

    for (int kt = 0; kt <= lastkt; kt++) {
        const int slot = kt % 3;
        cp_wait<1>();
        __syncthreads();

        // ---- S = Q K^T (tensor work first) ----
        const uint32_t ksb = sbase + slot * 2 * FTILE;
        float s[8][4];
        #pragma unroll
        for (int nt = 0; nt < 8; nt++)
            #pragma unroll
            for (int j = 0; j < 4; j++) s[nt][j] = 0.0f;

        #pragma unroll
        for (int nt = 0; nt < 8; nt++) {
            const uint32_t abase = ksb + (nt * 8 + krow) * FROWB + ktil;
            #pragma unroll
            for (int hh = 0; hh < 2; hh++) {
                uint32_t b0, b1, b2, b3;
                ldsm4(b0, b1, b2, b3, abase + hh * 64);
                mma_f16(s[nt], qa[2 * hh],     b0, b1);
                mma_f16(s[nt], qa[2 * hh + 1], b2, b3);
            }
        }

        // prefetch tile kt+2 into slot (kt+2)%3
        if (kt + 2 <= lastkt) AFILL(kt + 2, (kt + 2) % 3);
        cp_commit();

        // ---- causal mask (last two tiles only) ----
        if (kt >= 2 * qb) {
            const int rg = qb * 128 + wm + lr;
            #pragma unroll
            for (int nt = 0; nt < 8; nt++) {
                const int cg = kt * 64 + nt * 8 + 2 * lc;
                if (cg     > rg)     s[nt][0] = -1e30f;
                if (cg + 1 > rg)     s[nt][1] = -1e30f;
                if (cg     > rg + 8) s[nt][2] = -1e30f;
                if (cg + 1 > rg + 8) s[nt][3] = -1e30f;
            }
        }

        // ---- online softmax, exp2 domain, packed f16 exponentials ----
        float mx0 = -INFINITY, mx1 = -INFINITY;
        #pragma unroll
        for (int nt = 0; nt < 8; nt++) {
            mx0 = fmaxf(mx0, fmaxf(s[nt][0], s[nt][1]));
            mx1 = fmaxf(mx1, fmaxf(s[nt][2], s[nt][3]));
        }
        mx0 = fmaxf(mx0, __shfl_xor_sync(0xffffffffu, mx0, 1));
        mx0 = fmaxf(mx0, __shfl_xor_sync(0xffffffffu, mx0, 2));
        mx1 = fmaxf(mx1, __shfl_xor_sync(0xffffffffu, mx1, 1));
        mx1 = fmaxf(mx1, __shfl_xor_sync(0xffffffffu, mx1, 2));

        const float m0n = fmaxf(m0, mx0);
        const float m1n = fmaxf(m1, mx1);
        const float c0 = exp2f(m0 - m0n);
        const float c1 = exp2f(m1 - m1n);
        m0 = m0n; m1 = m1n;
        #pragma unroll
        for (int nt = 0; nt < 8; nt++) {
            o[nt][0] *= c0; o[nt][1] *= c0;
            o[nt][2] *= c1; o[nt][3] *= c1;
        }

        uint32_t ph[8][2];
        float la0 = 0.f, lb0 = 0.f, la1 = 0.f, lb1 = 0.f;
        #pragma unroll
        for (int nt = 0; nt < 8; nt++) {
            ph[nt][0] = ex2_h2(s[nt][0] - m0, s[nt][1] - m0);
            ph[nt][1] = ex2_h2(s[nt][2] - m1, s[nt][3] - m1);
            const float2 f0 = __half22float2(*(__half2*)&ph[nt][0]);
            const float2 f1 = __half22float2(*(__half2*)&ph[nt][1]);
            if (nt & 1) { lb0 += f0.x + f0.y; lb1 += f1.x + f1.y; }
            else        { la0 += f0.x + f0.y; la1 += f1.x + f1.y; }
        }
        l0 = l0 * c0 + (la0 + lb0);
        l1 = l1 * c1 + (la1 + lb1);

        // ---- O += P V (ph IS the A-fragment) ----
        const uint32_t vsl = ksb + FTILE;
        #pragma unroll
        for (int kk = 0; kk < 4; kk++) {
            uint32_t pa[4];
            pa[0] = ph[2 * kk][0];
            pa[1] = ph[2 * kk][1];
            pa[2] = ph[2 * kk + 1][0];
            pa[3] = ph[2 * kk + 1][1];
            const uint32_t vaddr0 = vsl + (kk * 16 + vrow) * FROWB + voff;
            #pragma unroll
            for (int j = 0; j < 4; j++) {
                uint32_t v0, v1, v2, v3;
                ldsm4t(v0, v1, v2, v3, vaddr0 + j * 32);
                mma_f16(o[2 * j],     pa, v0, v1);
                mma_f16(o[2 * j + 1], pa, v2, v3);
            }
        }
    }

    // ---- finalize ----
    l0 += __shfl_xor_sync(0xffffffffu, l0, 1);
    l0 += __shfl_xor_sync(0xffffffffu, l0, 2);
    l1 += __shfl_xor_sync(0xffffffffu, l1, 1);
    l1 += __shfl_xor_sync(0xffffffffu, l1, 2);
    const float i0 = 1.0f / l0;
    const float i1 = 1.0f / l1;

    const int row0 = qb * 128 + wm + lr;
    uint32_t* op0 = (uint32_t*)(Oh + base + (size_t)row0 * EMB);
    uint32_t* op1 = (uint32_t*)(Oh + base + (size_t)(row0 + 8) * EMB);
    #pragma unroll
    for (int ntd = 0; ntd < 8; ntd++) {
        const int colw = ntd * 4 + lc;
        op0[colw] = pack_h2(o[ntd][0] * i0, o[ntd][1] * i0);
        op1[colw] = pack_h2(o[ntd][2] * i1, o[ntd][3] * i1);
    }
}

// ---------------------------------------------------------------------------
extern "C" void kernel_launch(void* const* d_in, const int* in_sizes, int n_in,
                              void* d_out, int out_size)
{
    const float* x   = (const float*)d_in[0];
    const float* Wk  = (const float*)d_in[1];
    const float* Wq  = (const float*)d_in[2];
    const float* Wv  = (const float*)d_in[3];
    const float* Wo  = (const float*)d_in[4];
    const float* bo  = (const float*)d_in[5];
    const float* kg  = (const float*)d_in[6];
    const float* kb  = (const float*)d_in[7];
    const float* qg  = (const float*)d_in[8];
    const float* qb  = (const float*)d_in[9];
    float* out = (float*)d_out;

    float* sbase = nullptr;
    cudaGetSymbolAddress((void**)&sbase, g_scratch);
    const size_t MB1 = 1024ull * 1024ull;
    __half* xh  = (__half*)(sbase);
    __half* wkh = (__half*)(sbase + 4 * MB1);
    __half* wqh = (__half*)(sbase + 4 * MB1 + MB1 / 2);
    __half* wvh = (__half*)(sbase + 5 * MB1);
    __half* woh = (__half*)(sbase + 5 * MB1 + MB1 / 2);
    __half* gkh = (__half*)(sbase + 6 * MB1);
    __half* gqh = (__half*)(sbase + 10 * MB1);
    __half* gvh = (__half*)(sbase + 14 * MB1);
    __half* gyh = (__half*)(sbase + 18 * MB1);

    const float SCALE  = 0.17677669529663687f;           // 1024^(-1/4)
    const float SCALEQ = SCALE * 1.4426950408889634f;    // fold log2(e) into Q

    cudaFuncSetAttribute(gemm_qkv,
                         cudaFuncAttributeMaxDynamicSharedMemorySize, GEMM_SMEM);
    cudaFuncSetAttribute(gemm_f16,
                         cudaFuncAttributeMaxDynamicSharedMemorySize, GEMM_SMEM);

    conv_all<<<2048, 256>>>(x, Wk, Wq, Wv, Wo, xh, wkh, wqh, wvh, woh);

    dim3 qkvGrid(3 * EMB / 128, MTOK / 128);   // (24, 64)
    gemm_qkv<<<qkvGrid, 256, GEMM_SMEM>>>(xh, wkh, wqh, wvh, gkh, gqh, gvh,
                                          kg, kb, qg, qb, SCALE, SCALEQ);

    dim3 attnGrid(SEQ / 128, HEADS, BATCH);    // (16, 16, 4)
    flash_attn2<<<attnGrid, 256>>>(gqh, gkh, gvh, gyh);

    dim3 gemmGrid(EMB / 128, MTOK / 128);      // (8, 64)
    gemm_f16<<<gemmGrid, 256, GEMM_SMEM>>>(gyh, woh, bo, out, MTOK, EMB, EMB);
}